// round 1
// baseline (speedup 1.0000x reference)
#include <cuda_runtime.h>
#include <math_constants.h>
#include <cstdint>
#include <cstddef>

// Problem constants
#define HH 8
#define KD 64
#define VD 64
#define KNN 128
#define DM 512
#define FCD 2048
#define NB 4
#define SSQ 1024
#define EPS 1e-5f

// ---------------- scratch (single __device__ array, no allocations) ----------------
constexpr size_t OFF_GDEC = 0;
constexpr size_t OFF_GENC = OFF_GDEC + (size_t)SSQ * SSQ;
constexpr size_t OFF_K    = OFF_GENC + (size_t)SSQ * SSQ;
constexpr size_t OFF_V    = OFF_K   + (size_t)HH * NB * SSQ * KD;
constexpr size_t OFF_Q    = OFF_V   + (size_t)HH * NB * SSQ * VD;
constexpr size_t OFF_CTX  = OFF_Q   + (size_t)HH * NB * SSQ * KD;
constexpr size_t OFF_H    = OFF_CTX + (size_t)NB * SSQ * DM;
constexpr size_t OFF_H2   = OFF_H   + (size_t)NB * SSQ * DM;
constexpr size_t OFF_T    = OFF_H2  + (size_t)NB * SSQ * DM;
constexpr size_t OFF_ATT  = OFF_T   + (size_t)NB * SSQ * FCD;
constexpr size_t SCRATCH_TOTAL = OFF_ATT + (size_t)HH * NB * SSQ * SSQ;

__device__ float g_scratch[SCRATCH_TOTAL];

// ---------------- generic batched GEMM: C = alpha*A@B(^T) [+bias][relu][+resid] ----------------
// A: [M,Kc] row-major (lda = Kc). B: non-trans [Kc,Nc] (ldb=Nc), trans [Nc,Kc] (ldb=Kc).
// Batch index z = zo*Bi + zi, pointer offsets per (zo, zi).
// All M multiples of 64, Nc multiples of 64, Kc multiples of 16 -> no bounds checks.
__global__ __launch_bounds__(256) void gemm_k(
    const float* __restrict__ A, const float* __restrict__ B, float* __restrict__ C,
    int Nc, int Kc, int ldc,
    long long sAo, long long sAi, long long sBo, long long sBi,
    long long sCo, long long sCi, int Bi,
    const float* __restrict__ bias, long long sBias,
    const float* __restrict__ resid, int ldr,
    float alpha, int transB, int relu)
{
    __shared__ float As[16][65];
    __shared__ float Bs[16][68];

    int z = blockIdx.z;
    int zo = z / Bi, zi = z - zo * Bi;
    A += (size_t)zo * sAo + (size_t)zi * sAi;
    B += (size_t)zo * sBo + (size_t)zi * sBi;
    C += (size_t)zo * sCo + (size_t)zi * sCi;
    const float* biasp = bias ? (bias + (size_t)zo * sBias) : nullptr;

    int bn0 = blockIdx.x * 64;
    int bm0 = blockIdx.y * 64;
    int t = threadIdx.x;
    int tx = t & 15, ty = t >> 4;

    float acc[4][4] = {};

    for (int k0 = 0; k0 < Kc; k0 += 16) {
        // load A tile 64x16
        #pragma unroll
        for (int i = 0; i < 4; i++) {
            int idx = t + i * 256;
            int r = idx >> 4, c = idx & 15;
            As[c][r] = A[(size_t)(bm0 + r) * Kc + k0 + c];
        }
        // load B tile 16x64
        if (!transB) {
            #pragma unroll
            for (int i = 0; i < 4; i++) {
                int idx = t + i * 256;
                int r = idx >> 6, c = idx & 63;
                Bs[r][c] = B[(size_t)(k0 + r) * Nc + bn0 + c];
            }
        } else {
            #pragma unroll
            for (int i = 0; i < 4; i++) {
                int idx = t + i * 256;
                int nn = idx >> 4, kk = idx & 15;
                Bs[kk][nn] = B[(size_t)(bn0 + nn) * Kc + k0 + kk];
            }
        }
        __syncthreads();

        #pragma unroll
        for (int k = 0; k < 16; k++) {
            float a[4], b[4];
            #pragma unroll
            for (int i = 0; i < 4; i++) a[i] = As[k][ty * 4 + i];
            #pragma unroll
            for (int j = 0; j < 4; j++) b[j] = Bs[k][tx * 4 + j];
            #pragma unroll
            for (int i = 0; i < 4; i++)
                #pragma unroll
                for (int j = 0; j < 4; j++)
                    acc[i][j] += a[i] * b[j];
        }
        __syncthreads();
    }

    #pragma unroll
    for (int i = 0; i < 4; i++) {
        int row = bm0 + ty * 4 + i;
        #pragma unroll
        for (int j = 0; j < 4; j++) {
            int col = bn0 + tx * 4 + j;
            float v = acc[i][j] * alpha;
            if (biasp) v += biasp[col];
            if (relu) v = fmaxf(v, 0.f);
            if (resid) v += resid[(size_t)row * ldr + col];
            C[(size_t)row * ldc + col] = v;
        }
    }
}

// ---------------- row softmax (graph preprocessing), rows of length SSQ ----------------
__global__ __launch_bounds__(256) void row_softmax_k(const float* __restrict__ in,
                                                     float* __restrict__ out)
{
    __shared__ float sh[8];
    int row = blockIdx.x;
    int t = threadIdx.x;
    int lane = t & 31, w = t >> 5;
    const float* rin = in + (size_t)row * SSQ;
    float* rout = out + (size_t)row * SSQ;

    float v[4];
    #pragma unroll
    for (int i = 0; i < 4; i++) v[i] = rin[t + i * 256];

    // block max
    float m = fmaxf(fmaxf(v[0], v[1]), fmaxf(v[2], v[3]));
    #pragma unroll
    for (int o = 16; o; o >>= 1) m = fmaxf(m, __shfl_xor_sync(0xffffffffu, m, o));
    if (lane == 0) sh[w] = m;
    __syncthreads();
    m = sh[0];
    #pragma unroll
    for (int i = 1; i < 8; i++) m = fmaxf(m, sh[i]);
    __syncthreads();

    float e[4]; float s = 0.f;
    #pragma unroll
    for (int i = 0; i < 4; i++) { e[i] = expf(v[i] - m); s += e[i]; }
    #pragma unroll
    for (int o = 16; o; o >>= 1) s += __shfl_xor_sync(0xffffffffu, s, o);
    if (lane == 0) sh[w] = s;
    __syncthreads();
    s = 0.f;
    #pragma unroll
    for (int i = 0; i < 8; i++) s += sh[i];
    float inv = 1.0f / s;
    #pragma unroll
    for (int i = 0; i < 4; i++) rout[t + i * 256] = e[i] * inv;
}

// ---------------- fused: causal mask + exact top-KNN threshold + softmax + graph blend ----------------
__device__ __forceinline__ unsigned f2key(float f) {
    unsigned u = __float_as_uint(f);
    return (u & 0x80000000u) ? ~u : (u | 0x80000000u);
}

__global__ __launch_bounds__(256) void attn_post_k(float* __restrict__ att,
                                                   const float* __restrict__ graph,
                                                   int masked, float gw)
{
    __shared__ float sredf[8];
    __shared__ unsigned scount[8];

    int q = blockIdx.x, n = blockIdx.y, h = blockIdx.z;
    float* row = att + (((size_t)(h * NB + n)) * SSQ + q) * SSQ;
    const float* grow = graph + (size_t)q * SSQ;
    int L = masked ? (q + 1) : SSQ;

    int t = threadIdx.x;
    int lane = t & 31, w = t >> 5;

    float v[4]; unsigned key[4]; bool valid[4];
    #pragma unroll
    for (int i = 0; i < 4; i++) {
        int idx = t + i * 256;
        valid[i] = idx < L;
        v[i] = valid[i] ? row[idx] : -CUDART_INF_F;
        key[i] = valid[i] ? f2key(v[i]) : 0u;
    }

    unsigned threshKey = 0;
    if (L > KNN) {
        unsigned lo = 0u, hi = 0xFFFFFFFFu;
        while (lo < hi) {
            unsigned mid = (unsigned)((((unsigned long long)lo + (unsigned long long)hi + 1ull)) >> 1);
            unsigned c = 0;
            #pragma unroll
            for (int i = 0; i < 4; i++) c += (key[i] >= mid) ? 1u : 0u;
            #pragma unroll
            for (int o = 16; o; o >>= 1) c += __shfl_xor_sync(0xffffffffu, c, o);
            if (lane == 0) scount[w] = c;
            __syncthreads();
            unsigned cnt = 0;
            #pragma unroll
            for (int i = 0; i < 8; i++) cnt += scount[i];
            __syncthreads();
            if (cnt >= KNN) lo = mid; else hi = mid - 1u;
        }
        threshKey = lo;
    }

    bool kept[4];
    #pragma unroll
    for (int i = 0; i < 4; i++)
        kept[i] = valid[i] && (L <= KNN || key[i] >= threshKey);

    // max over kept
    float m = -CUDART_INF_F;
    #pragma unroll
    for (int i = 0; i < 4; i++) if (kept[i]) m = fmaxf(m, v[i]);
    #pragma unroll
    for (int o = 16; o; o >>= 1) m = fmaxf(m, __shfl_xor_sync(0xffffffffu, m, o));
    if (lane == 0) sredf[w] = m;
    __syncthreads();
    m = sredf[0];
    #pragma unroll
    for (int i = 1; i < 8; i++) m = fmaxf(m, sredf[i]);
    __syncthreads();

    float e[4]; float s = 0.f;
    #pragma unroll
    for (int i = 0; i < 4; i++) {
        e[i] = kept[i] ? expf(v[i] - m) : 0.f;
        s += e[i];
    }
    #pragma unroll
    for (int o = 16; o; o >>= 1) s += __shfl_xor_sync(0xffffffffu, s, o);
    if (lane == 0) sredf[w] = s;
    __syncthreads();
    s = 0.f;
    #pragma unroll
    for (int i = 0; i < 8; i++) s += sredf[i];
    float inv = 1.0f / s;

    float og = 1.0f - gw;
    #pragma unroll
    for (int i = 0; i < 4; i++) {
        int idx = t + i * 256;
        row[idx] = gw * grow[idx] + og * (e[i] * inv);
    }
}

// ---------------- LayerNorm over rows of DM=512 (elementwise_affine=False) ----------------
__global__ __launch_bounds__(128) void layernorm_k(const float* __restrict__ in,
                                                   float* __restrict__ out)
{
    __shared__ float sh[4];
    int row = blockIdx.x;
    int t = threadIdx.x;
    int lane = t & 31, w = t >> 5;
    const float* rin = in + (size_t)row * DM;
    float* rout = out + (size_t)row * DM;

    float v[4];
    #pragma unroll
    for (int i = 0; i < 4; i++) v[i] = rin[t + i * 128];

    float s = v[0] + v[1] + v[2] + v[3];
    #pragma unroll
    for (int o = 16; o; o >>= 1) s += __shfl_xor_sync(0xffffffffu, s, o);
    if (lane == 0) sh[w] = s;
    __syncthreads();
    s = sh[0] + sh[1] + sh[2] + sh[3];
    float mean = s * (1.0f / DM);
    __syncthreads();

    float sq = 0.f;
    #pragma unroll
    for (int i = 0; i < 4; i++) { float d = v[i] - mean; sq += d * d; }
    #pragma unroll
    for (int o = 16; o; o >>= 1) sq += __shfl_xor_sync(0xffffffffu, sq, o);
    if (lane == 0) sh[w] = sq;
    __syncthreads();
    sq = sh[0] + sh[1] + sh[2] + sh[3];
    float var = sq * (1.0f / DM);
    float inv = rsqrtf(var + EPS);

    #pragma unroll
    for (int i = 0; i < 4; i++) rout[t + i * 128] = (v[i] - mean) * inv;
}

// ---------------- host-side helpers ----------------
static inline void gemm(const float* A, const float* B, float* C,
                        int M, int Nc, int Kc, int ldc,
                        long long sAo, long long sAi, long long sBo, long long sBi,
                        long long sCo, long long sCi, int Bo, int Bi,
                        const float* bias, long long sBias,
                        const float* resid, int ldr,
                        float alpha, int transB, int relu)
{
    dim3 grid(Nc / 64, M / 64, Bo * Bi), block(256);
    gemm_k<<<grid, block>>>(A, B, C, Nc, Kc, ldc, sAo, sAi, sBo, sBi, sCo, sCi, Bi,
                            bias, sBias, resid, ldr, alpha, transB, relu);
}

extern "C" void kernel_launch(void* const* d_in, const int* in_sizes, int n_in,
                              void* d_out, int out_size)
{
    (void)in_sizes; (void)n_in; (void)out_size;
    const float* z        = (const float*)d_in[0];
    const float* y        = (const float*)d_in[1];
    const float* graphDec = (const float*)d_in[2];
    const float* graphEnc = (const float*)d_in[3];
    const float* dec_Wk   = (const float*)d_in[4];
    const float* dec_bk   = (const float*)d_in[5];
    const float* dec_Wv   = (const float*)d_in[6];
    const float* dec_bv   = (const float*)d_in[7];
    const float* dec_Wo   = (const float*)d_in[8];
    const float* dec_bo   = (const float*)d_in[9];
    const float* enc_Wk   = (const float*)d_in[10];
    const float* enc_bk   = (const float*)d_in[11];
    const float* enc_Wq   = (const float*)d_in[12];
    const float* enc_bq   = (const float*)d_in[13];
    const float* enc_Wv   = (const float*)d_in[14];
    const float* enc_bv   = (const float*)d_in[15];
    const float* enc_Wo   = (const float*)d_in[16];
    const float* enc_bo   = (const float*)d_in[17];
    const float* fc_W1    = (const float*)d_in[18];
    const float* fc_b1    = (const float*)d_in[19];
    const float* fc_W2    = (const float*)d_in[20];
    const float* fc_b2    = (const float*)d_in[21];
    float* out = (float*)d_out;

    float* sc = nullptr;
    cudaGetSymbolAddress((void**)&sc, g_scratch);
    float* gdec = sc + OFF_GDEC;
    float* genc = sc + OFF_GENC;
    float* gK   = sc + OFF_K;
    float* gV   = sc + OFF_V;
    float* gQ   = sc + OFF_Q;
    float* gCtx = sc + OFF_CTX;
    float* gH   = sc + OFF_H;
    float* gH2  = sc + OFF_H2;
    float* gT   = sc + OFF_T;
    float* gAtt = sc + OFF_ATT;

    const int M = NB * SSQ;               // 4096
    const long long sKh = (long long)NB * SSQ * KD;  // per-head stride in K/V/Q
    const long long sKn = (long long)SSQ * KD;       // per-batch stride
    const long long sAh = (long long)NB * SSQ * SSQ; // att per-head
    const long long sAn = (long long)SSQ * SSQ;      // att per-batch
    const float inv_scale = 0.125f;       // 1/sqrt(64)

    // 0) graph row-softmax
    row_softmax_k<<<SSQ, 256>>>(graphDec, gdec);
    row_softmax_k<<<SSQ, 256>>>(graphEnc, genc);

    // ---------- stage 1: masked decoder self-attention on y ----------
    // K = y @ Wk + bk, per head (query = key)
    gemm(y, dec_Wk, gK, M, KD, DM, KD, 0, 0, (long long)DM * KD, 0, sKh, 0, HH, 1,
         dec_bk, KD, nullptr, 0, 1.0f, 0, 0);
    gemm(y, dec_Wv, gV, M, VD, DM, VD, 0, 0, (long long)DM * VD, 0, sKh, 0, HH, 1,
         dec_bv, VD, nullptr, 0, 1.0f, 0, 0);
    // scores = K @ K^T / 8   (batched over h,n)
    gemm(gK, gK, gAtt, SSQ, SSQ, KD, SSQ, sKh, sKn, sKh, sKn, sAh, sAn, HH, NB,
         nullptr, 0, nullptr, 0, inv_scale, 1, 0);
    // mask + top-KNN + softmax + blend with gdec
    attn_post_k<<<dim3(SSQ, NB, HH), 256>>>(gAtt, gdec, 1, 0.5f);
    // ctx = att @ V, scattered into [n, q, h*VD+v]
    gemm(gAtt, gV, gCtx, SSQ, VD, SSQ, DM, sAh, sAn, sKh, sKn, (long long)VD, (long long)SSQ * DM,
         HH, NB, nullptr, 0, nullptr, 0, 1.0f, 0, 0);
    // out-proj + bias + residual(y)
    gemm(gCtx, dec_Wo, gH, M, DM, DM, DM, 0, 0, 0, 0, 0, 0, 1, 1,
         dec_bo, 0, y, DM, 1.0f, 0, 0);
    layernorm_k<<<M, 128>>>(gH, gH);      // gH = h

    // ---------- stage 2: encoder-decoder attention (K,V from z, Q from h) ----------
    gemm(z, enc_Wk, gK, M, KD, DM, KD, 0, 0, (long long)DM * KD, 0, sKh, 0, HH, 1,
         enc_bk, KD, nullptr, 0, 1.0f, 0, 0);
    gemm(z, enc_Wv, gV, M, VD, DM, VD, 0, 0, (long long)DM * VD, 0, sKh, 0, HH, 1,
         enc_bv, VD, nullptr, 0, 1.0f, 0, 0);
    gemm(gH, enc_Wq, gQ, M, KD, DM, KD, 0, 0, (long long)DM * KD, 0, sKh, 0, HH, 1,
         enc_bq, KD, nullptr, 0, 1.0f, 0, 0);
    gemm(gQ, gK, gAtt, SSQ, SSQ, KD, SSQ, sKh, sKn, sKh, sKn, sAh, sAn, HH, NB,
         nullptr, 0, nullptr, 0, inv_scale, 1, 0);
    attn_post_k<<<dim3(SSQ, NB, HH), 256>>>(gAtt, genc, 0, 0.5f);
    gemm(gAtt, gV, gCtx, SSQ, VD, SSQ, DM, sAh, sAn, sKh, sKn, (long long)VD, (long long)SSQ * DM,
         HH, NB, nullptr, 0, nullptr, 0, 1.0f, 0, 0);
    gemm(gCtx, enc_Wo, gH2, M, DM, DM, DM, 0, 0, 0, 0, 0, 0, 1, 1,
         enc_bo, 0, gH, DM, 1.0f, 0, 0);
    layernorm_k<<<M, 128>>>(gH2, gH2);    // gH2 = h2

    // ---------- stage 3: MLP ----------
    gemm(gH2, fc_W1, gT, M, FCD, DM, FCD, 0, 0, 0, 0, 0, 0, 1, 1,
         fc_b1, 0, nullptr, 0, 1.0f, 0, 1);                 // relu
    gemm(gT, fc_W2, gH, M, DM, FCD, DM, 0, 0, 0, 0, 0, 0, 1, 1,
         fc_b2, 0, gH2, DM, 1.0f, 0, 0);                    // + residual h2
    layernorm_k<<<M, 128>>>(gH, out);
}

// round 4
// speedup vs baseline: 1.6165x; 1.6165x over previous
#include <cuda_runtime.h>
#include <math_constants.h>
#include <cstdint>
#include <cstddef>

// Problem constants
#define HH 8
#define KD 64
#define VD 64
#define KNN 128
#define DM 512
#define FCD 2048
#define NB 4
#define SSQ 1024
#define EPS 1e-5f

// ---------------- scratch (single __device__ array, no allocations) ----------------
constexpr size_t OFF_GDEC = 0;
constexpr size_t OFF_GENC = OFF_GDEC + (size_t)SSQ * SSQ;
constexpr size_t OFF_K    = OFF_GENC + (size_t)SSQ * SSQ;
constexpr size_t OFF_V    = OFF_K   + (size_t)HH * NB * SSQ * KD;
constexpr size_t OFF_Q    = OFF_V   + (size_t)HH * NB * SSQ * VD;
constexpr size_t OFF_CTX  = OFF_Q   + (size_t)HH * NB * SSQ * KD;
constexpr size_t OFF_H    = OFF_CTX + (size_t)NB * SSQ * DM;
constexpr size_t OFF_H2   = OFF_H   + (size_t)NB * SSQ * DM;
constexpr size_t OFF_T    = OFF_H2  + (size_t)NB * SSQ * DM;
constexpr size_t OFF_ATT  = OFF_T   + (size_t)NB * SSQ * FCD;
constexpr size_t SCRATCH_TOTAL = OFF_ATT + (size_t)HH * NB * SSQ * SSQ;

__device__ float g_scratch[SCRATCH_TOTAL];

// ---------------- batched GEMM: C = alpha*A@B(^T) [+bias][relu][+resid] ----------------
// Block tile 128(M) x 64(N), K-tile 16, 256 threads, 8x4 micro-tile,
// double-buffered smem, float4 global loads + register prefetch.
// Requirements: M % 128 == 0, Nc % 64 == 0, Kc % 16 == 0 (true for all calls).
__global__ __launch_bounds__(256) void gemm_k(
    const float* __restrict__ A, const float* __restrict__ B, float* __restrict__ C,
    int Nc, int Kc, int ldc,
    long long sAo, long long sAi, long long sBo, long long sBi,
    long long sCo, long long sCi, int Bi,
    const float* __restrict__ bias, long long sBias,
    const float* __restrict__ resid, int ldr,
    float alpha, int transB, int relu)
{
    __shared__ float As[2][16][132];   // [buf][k][m], padded rows
    __shared__ float Bs[2][16][64];    // [buf][k][n]

    int z = blockIdx.z;
    int zo = z / Bi, zi = z - zo * Bi;
    A += (size_t)zo * sAo + (size_t)zi * sAi;
    B += (size_t)zo * sBo + (size_t)zi * sBi;
    C += (size_t)zo * sCo + (size_t)zi * sCi;
    const float* biasp = bias ? (bias + (size_t)zo * sBias) : nullptr;

    int bn0 = blockIdx.x * 64;
    int bm0 = blockIdx.y * 128;
    int t = threadIdx.x;
    int tx = t & 15, ty = t >> 4;

    // A-load mapping: li in [0,512): row = li>>2 (0..127), kq = li&3 (float4 along K)
    int a_row0 = t >> 2,         a_kq0 = t & 3;
    int a_row1 = (t + 256) >> 2, a_kq1 = (t + 256) & 3;
    // B non-trans mapping: kk = t>>4 (0..15), nq = t&15 (float4 along N)
    int b_kk = t >> 4, b_nq = t & 15;
    // B trans mapping: n = t>>2 (0..63), kq = t&3 (float4 along K)
    int bt_n = t >> 2, bt_kq = t & 3;

    float acc[8][4] = {};

    // ---- prologue: tile 0 ----
    {
        float4 v0 = *(const float4*)&A[(size_t)(bm0 + a_row0) * Kc + a_kq0 * 4];
        float4 v1 = *(const float4*)&A[(size_t)(bm0 + a_row1) * Kc + a_kq1 * 4];
        As[0][a_kq0 * 4 + 0][a_row0] = v0.x; As[0][a_kq0 * 4 + 1][a_row0] = v0.y;
        As[0][a_kq0 * 4 + 2][a_row0] = v0.z; As[0][a_kq0 * 4 + 3][a_row0] = v0.w;
        As[0][a_kq1 * 4 + 0][a_row1] = v1.x; As[0][a_kq1 * 4 + 1][a_row1] = v1.y;
        As[0][a_kq1 * 4 + 2][a_row1] = v1.z; As[0][a_kq1 * 4 + 3][a_row1] = v1.w;
        if (!transB) {
            float4 v = *(const float4*)&B[(size_t)b_kk * Nc + bn0 + b_nq * 4];
            *(float4*)&Bs[0][b_kk][b_nq * 4] = v;
        } else {
            float4 v = *(const float4*)&B[(size_t)(bn0 + bt_n) * Kc + bt_kq * 4];
            Bs[0][bt_kq * 4 + 0][bt_n] = v.x; Bs[0][bt_kq * 4 + 1][bt_n] = v.y;
            Bs[0][bt_kq * 4 + 2][bt_n] = v.z; Bs[0][bt_kq * 4 + 3][bt_n] = v.w;
        }
    }
    __syncthreads();

    int nT = Kc >> 4;
    int cur = 0;
    for (int tt = 0; tt < nT; tt++) {
        float4 pa0, pa1, pb;
        bool has = (tt + 1) < nT;
        if (has) {
            int k0 = (tt + 1) << 4;
            pa0 = *(const float4*)&A[(size_t)(bm0 + a_row0) * Kc + k0 + a_kq0 * 4];
            pa1 = *(const float4*)&A[(size_t)(bm0 + a_row1) * Kc + k0 + a_kq1 * 4];
            if (!transB)
                pb = *(const float4*)&B[(size_t)(k0 + b_kk) * Nc + bn0 + b_nq * 4];
            else
                pb = *(const float4*)&B[(size_t)(bn0 + bt_n) * Kc + k0 + bt_kq * 4];
        }

        #pragma unroll
        for (int k = 0; k < 16; k++) {
            float4 a0 = *(const float4*)&As[cur][k][ty * 8];
            float4 a1 = *(const float4*)&As[cur][k][ty * 8 + 4];
            float4 b  = *(const float4*)&Bs[cur][k][tx * 4];
            float av[8] = {a0.x, a0.y, a0.z, a0.w, a1.x, a1.y, a1.z, a1.w};
            float bv[4] = {b.x, b.y, b.z, b.w};
            #pragma unroll
            for (int i = 0; i < 8; i++)
                #pragma unroll
                for (int j = 0; j < 4; j++)
                    acc[i][j] += av[i] * bv[j];
        }

        if (has) {
            int nxt = cur ^ 1;
            As[nxt][a_kq0 * 4 + 0][a_row0] = pa0.x; As[nxt][a_kq0 * 4 + 1][a_row0] = pa0.y;
            As[nxt][a_kq0 * 4 + 2][a_row0] = pa0.z; As[nxt][a_kq0 * 4 + 3][a_row0] = pa0.w;
            As[nxt][a_kq1 * 4 + 0][a_row1] = pa1.x; As[nxt][a_kq1 * 4 + 1][a_row1] = pa1.y;
            As[nxt][a_kq1 * 4 + 2][a_row1] = pa1.z; As[nxt][a_kq1 * 4 + 3][a_row1] = pa1.w;
            if (!transB) {
                *(float4*)&Bs[nxt][b_kk][b_nq * 4] = pb;
            } else {
                Bs[nxt][bt_kq * 4 + 0][bt_n] = pb.x; Bs[nxt][bt_kq * 4 + 1][bt_n] = pb.y;
                Bs[nxt][bt_kq * 4 + 2][bt_n] = pb.z; Bs[nxt][bt_kq * 4 + 3][bt_n] = pb.w;
            }
            __syncthreads();
            cur = nxt;
        }
    }

    // ---- epilogue ----
    int col = bn0 + tx * 4;
    float4 bv = make_float4(0.f, 0.f, 0.f, 0.f);
    if (biasp) bv = *(const float4*)&biasp[col];
    #pragma unroll
    for (int i = 0; i < 8; i++) {
        int row = bm0 + ty * 8 + i;
        float4 v;
        v.x = acc[i][0] * alpha + bv.x;
        v.y = acc[i][1] * alpha + bv.y;
        v.z = acc[i][2] * alpha + bv.z;
        v.w = acc[i][3] * alpha + bv.w;
        if (relu) {
            v.x = fmaxf(v.x, 0.f); v.y = fmaxf(v.y, 0.f);
            v.z = fmaxf(v.z, 0.f); v.w = fmaxf(v.w, 0.f);
        }
        if (resid) {
            float4 r = *(const float4*)&resid[(size_t)row * ldr + col];
            v.x += r.x; v.y += r.y; v.z += r.z; v.w += r.w;
        }
        *(float4*)&C[(size_t)row * ldc + col] = v;
    }
}

// ---------------- row softmax (graph preprocessing), rows of length SSQ ----------------
__global__ __launch_bounds__(256) void row_softmax_k(const float* __restrict__ in,
                                                     float* __restrict__ out)
{
    __shared__ float sh[8];
    int row = blockIdx.x;
    int t = threadIdx.x;
    int lane = t & 31, w = t >> 5;
    const float* rin = in + (size_t)row * SSQ;
    float* rout = out + (size_t)row * SSQ;

    float v[4];
    #pragma unroll
    for (int i = 0; i < 4; i++) v[i] = rin[t + i * 256];

    float m = fmaxf(fmaxf(v[0], v[1]), fmaxf(v[2], v[3]));
    #pragma unroll
    for (int o = 16; o; o >>= 1) m = fmaxf(m, __shfl_xor_sync(0xffffffffu, m, o));
    if (lane == 0) sh[w] = m;
    __syncthreads();
    m = sh[0];
    #pragma unroll
    for (int i = 1; i < 8; i++) m = fmaxf(m, sh[i]);
    __syncthreads();

    float e[4]; float s = 0.f;
    #pragma unroll
    for (int i = 0; i < 4; i++) { e[i] = expf(v[i] - m); s += e[i]; }
    #pragma unroll
    for (int o = 16; o; o >>= 1) s += __shfl_xor_sync(0xffffffffu, s, o);
    if (lane == 0) sh[w] = s;
    __syncthreads();
    s = 0.f;
    #pragma unroll
    for (int i = 0; i < 8; i++) s += sh[i];
    float inv = 1.0f / s;
    #pragma unroll
    for (int i = 0; i < 4; i++) rout[t + i * 256] = e[i] * inv;
}

// ---------------- fused: causal mask + exact top-KNN threshold + softmax + graph blend ----------------
__device__ __forceinline__ unsigned f2key(float f) {
    unsigned u = __float_as_uint(f);
    return (u & 0x80000000u) ? ~u : (u | 0x80000000u);
}

__global__ __launch_bounds__(256) void attn_post_k(float* __restrict__ att,
                                                   const float* __restrict__ graph,
                                                   int masked, float gw)
{
    __shared__ float sredf[8];
    __shared__ unsigned scount[2][8];

    int q = blockIdx.x, n = blockIdx.y, h = blockIdx.z;
    float* row = att + (((size_t)(h * NB + n)) * SSQ + q) * SSQ;
    const float* grow = graph + (size_t)q * SSQ;
    int L = masked ? (q + 1) : SSQ;

    int t = threadIdx.x;
    int lane = t & 31, w = t >> 5;

    float v[4]; unsigned key[4]; bool valid[4];
    #pragma unroll
    for (int i = 0; i < 4; i++) {
        int idx = t + i * 256;
        valid[i] = idx < L;
        v[i] = valid[i] ? row[idx] : -CUDART_INF_F;
        key[i] = valid[i] ? f2key(v[i]) : 0u;
    }

    unsigned threshKey = 0;
    if (L > KNN) {
        unsigned lo = 0u, hi = 0xFFFFFFFFu;
        unsigned it = 0;
        while (lo < hi) {
            unsigned mid = (unsigned)((((unsigned long long)lo + (unsigned long long)hi + 1ull)) >> 1);
            unsigned c = 0;
            #pragma unroll
            for (int i = 0; i < 4; i++) c += (key[i] >= mid) ? 1u : 0u;
            #pragma unroll
            for (int o = 16; o; o >>= 1) c += __shfl_xor_sync(0xffffffffu, c, o);
            unsigned* sc = scount[it & 1];
            if (lane == 0) sc[w] = c;
            __syncthreads();
            unsigned cnt = 0;
            #pragma unroll
            for (int i = 0; i < 8; i++) cnt += sc[i];
            if (cnt >= KNN) lo = mid; else hi = mid - 1u;
            it++;
        }
        threshKey = lo;
    }

    bool kept[4];
    #pragma unroll
    for (int i = 0; i < 4; i++)
        kept[i] = valid[i] && (L <= KNN || key[i] >= threshKey);

    float m = -CUDART_INF_F;
    #pragma unroll
    for (int i = 0; i < 4; i++) if (kept[i]) m = fmaxf(m, v[i]);
    #pragma unroll
    for (int o = 16; o; o >>= 1) m = fmaxf(m, __shfl_xor_sync(0xffffffffu, m, o));
    __syncthreads();   // protect sredf reuse vs earlier scount reads
    if (lane == 0) sredf[w] = m;
    __syncthreads();
    m = sredf[0];
    #pragma unroll
    for (int i = 1; i < 8; i++) m = fmaxf(m, sredf[i]);
    __syncthreads();

    float e[4]; float s = 0.f;
    #pragma unroll
    for (int i = 0; i < 4; i++) {
        e[i] = kept[i] ? expf(v[i] - m) : 0.f;
        s += e[i];
    }
    #pragma unroll
    for (int o = 16; o; o >>= 1) s += __shfl_xor_sync(0xffffffffu, s, o);
    if (lane == 0) sredf[w] = s;
    __syncthreads();
    s = 0.f;
    #pragma unroll
    for (int i = 0; i < 8; i++) s += sredf[i];
    float inv = 1.0f / s;

    float og = 1.0f - gw;
    #pragma unroll
    for (int i = 0; i < 4; i++) {
        int idx = t + i * 256;
        row[idx] = gw * grow[idx] + og * (e[i] * inv);
    }
}

// ---------------- LayerNorm over rows of DM=512 (elementwise_affine=False) ----------------
__global__ __launch_bounds__(128) void layernorm_k(const float* __restrict__ in,
                                                   float* __restrict__ out)
{
    __shared__ float sh[4];
    int row = blockIdx.x;
    int t = threadIdx.x;
    int lane = t & 31, w = t >> 5;
    const float* rin = in + (size_t)row * DM;
    float* rout = out + (size_t)row * DM;

    float v[4];
    #pragma unroll
    for (int i = 0; i < 4; i++) v[i] = rin[t + i * 128];

    float s = v[0] + v[1] + v[2] + v[3];
    #pragma unroll
    for (int o = 16; o; o >>= 1) s += __shfl_xor_sync(0xffffffffu, s, o);
    if (lane == 0) sh[w] = s;
    __syncthreads();
    s = sh[0] + sh[1] + sh[2] + sh[3];
    float mean = s * (1.0f / DM);
    __syncthreads();

    float sq = 0.f;
    #pragma unroll
    for (int i = 0; i < 4; i++) { float d = v[i] - mean; sq += d * d; }
    #pragma unroll
    for (int o = 16; o; o >>= 1) sq += __shfl_xor_sync(0xffffffffu, sq, o);
    if (lane == 0) sh[w] = sq;
    __syncthreads();
    sq = sh[0] + sh[1] + sh[2] + sh[3];
    float var = sq * (1.0f / DM);
    float inv = rsqrtf(var + EPS);

    #pragma unroll
    for (int i = 0; i < 4; i++) rout[t + i * 128] = (v[i] - mean) * inv;
}

// ---------------- host-side helpers ----------------
static inline void gemm(const float* A, const float* B, float* C,
                        int M, int Nc, int Kc, int ldc,
                        long long sAo, long long sAi, long long sBo, long long sBi,
                        long long sCo, long long sCi, int Bo, int Bi,
                        const float* bias, long long sBias,
                        const float* resid, int ldr,
                        float alpha, int transB, int relu)
{
    dim3 grid(Nc / 64, M / 128, Bo * Bi), block(256);
    gemm_k<<<grid, block>>>(A, B, C, Nc, Kc, ldc, sAo, sAi, sBo, sBi, sCo, sCi, Bi,
                            bias, sBias, resid, ldr, alpha, transB, relu);
}

extern "C" void kernel_launch(void* const* d_in, const int* in_sizes, int n_in,
                              void* d_out, int out_size)
{
    (void)in_sizes; (void)n_in; (void)out_size;
    const float* z        = (const float*)d_in[0];
    const float* y        = (const float*)d_in[1];
    const float* graphDec = (const float*)d_in[2];
    const float* graphEnc = (const float*)d_in[3];
    const float* dec_Wk   = (const float*)d_in[4];
    const float* dec_bk   = (const float*)d_in[5];
    const float* dec_Wv   = (const float*)d_in[6];
    const float* dec_bv   = (const float*)d_in[7];
    const float* dec_Wo   = (const float*)d_in[8];
    const float* dec_bo   = (const float*)d_in[9];
    const float* enc_Wk   = (const float*)d_in[10];
    const float* enc_bk   = (const float*)d_in[11];
    const float* enc_Wq   = (const float*)d_in[12];
    const float* enc_bq   = (const float*)d_in[13];
    const float* enc_Wv   = (const float*)d_in[14];
    const float* enc_bv   = (const float*)d_in[15];
    const float* enc_Wo   = (const float*)d_in[16];
    const float* enc_bo   = (const float*)d_in[17];
    const float* fc_W1    = (const float*)d_in[18];
    const float* fc_b1    = (const float*)d_in[19];
    const float* fc_W2    = (const float*)d_in[20];
    const float* fc_b2    = (const float*)d_in[21];
    float* out = (float*)d_out;

    float* sc = nullptr;
    cudaGetSymbolAddress((void**)&sc, g_scratch);
    float* gdec = sc + OFF_GDEC;
    float* genc = sc + OFF_GENC;
    float* gK   = sc + OFF_K;
    float* gV   = sc + OFF_V;
    float* gQ   = sc + OFF_Q;
    float* gCtx = sc + OFF_CTX;
    float* gH   = sc + OFF_H;
    float* gH2  = sc + OFF_H2;
    float* gT   = sc + OFF_T;
    float* gAtt = sc + OFF_ATT;

    const int M = NB * SSQ;               // 4096
    const long long sKh = (long long)NB * SSQ * KD;  // per-head stride in K/V/Q
    const long long sKn = (long long)SSQ * KD;       // per-batch stride
    const long long sAh = (long long)NB * SSQ * SSQ; // att per-head
    const long long sAn = (long long)SSQ * SSQ;      // att per-batch
    const float inv_scale = 0.125f;       // 1/sqrt(64)

    // 0) graph row-softmax
    row_softmax_k<<<SSQ, 256>>>(graphDec, gdec);
    row_softmax_k<<<SSQ, 256>>>(graphEnc, genc);

    // ---------- stage 1: masked decoder self-attention on y ----------
    gemm(y, dec_Wk, gK, M, KD, DM, KD, 0, 0, (long long)DM * KD, 0, sKh, 0, HH, 1,
         dec_bk, KD, nullptr, 0, 1.0f, 0, 0);
    gemm(y, dec_Wv, gV, M, VD, DM, VD, 0, 0, (long long)DM * VD, 0, sKh, 0, HH, 1,
         dec_bv, VD, nullptr, 0, 1.0f, 0, 0);
    gemm(gK, gK, gAtt, SSQ, SSQ, KD, SSQ, sKh, sKn, sKh, sKn, sAh, sAn, HH, NB,
         nullptr, 0, nullptr, 0, inv_scale, 1, 0);
    attn_post_k<<<dim3(SSQ, NB, HH), 256>>>(gAtt, gdec, 1, 0.5f);
    gemm(gAtt, gV, gCtx, SSQ, VD, SSQ, DM, sAh, sAn, sKh, sKn, (long long)VD, (long long)SSQ * DM,
         HH, NB, nullptr, 0, nullptr, 0, 1.0f, 0, 0);
    gemm(gCtx, dec_Wo, gH, M, DM, DM, DM, 0, 0, 0, 0, 0, 0, 1, 1,
         dec_bo, 0, y, DM, 1.0f, 0, 0);
    layernorm_k<<<M, 128>>>(gH, gH);      // gH = h

    // ---------- stage 2: encoder-decoder attention (K,V from z, Q from h) ----------
    gemm(z, enc_Wk, gK, M, KD, DM, KD, 0, 0, (long long)DM * KD, 0, sKh, 0, HH, 1,
         enc_bk, KD, nullptr, 0, 1.0f, 0, 0);
    gemm(z, enc_Wv, gV, M, VD, DM, VD, 0, 0, (long long)DM * VD, 0, sKh, 0, HH, 1,
         enc_bv, VD, nullptr, 0, 1.0f, 0, 0);
    gemm(gH, enc_Wq, gQ, M, KD, DM, KD, 0, 0, (long long)DM * KD, 0, sKh, 0, HH, 1,
         enc_bq, KD, nullptr, 0, 1.0f, 0, 0);
    gemm(gQ, gK, gAtt, SSQ, SSQ, KD, SSQ, sKh, sKn, sKh, sKn, sAh, sAn, HH, NB,
         nullptr, 0, nullptr, 0, inv_scale, 1, 0);
    attn_post_k<<<dim3(SSQ, NB, HH), 256>>>(gAtt, genc, 0, 0.5f);
    gemm(gAtt, gV, gCtx, SSQ, VD, SSQ, DM, sAh, sAn, sKh, sKn, (long long)VD, (long long)SSQ * DM,
         HH, NB, nullptr, 0, nullptr, 0, 1.0f, 0, 0);
    gemm(gCtx, enc_Wo, gH2, M, DM, DM, DM, 0, 0, 0, 0, 0, 0, 1, 1,
         enc_bo, 0, gH, DM, 1.0f, 0, 0);
    layernorm_k<<<M, 128>>>(gH2, gH2);    // gH2 = h2

    // ---------- stage 3: MLP ----------
    gemm(gH2, fc_W1, gT, M, FCD, DM, FCD, 0, 0, 0, 0, 0, 0, 1, 1,
         fc_b1, 0, nullptr, 0, 1.0f, 0, 1);                 // relu
    gemm(gT, fc_W2, gH, M, DM, FCD, DM, 0, 0, 0, 0, 0, 0, 1, 1,
         fc_b2, 0, gH2, DM, 1.0f, 0, 0);                    // + residual h2
    layernorm_k<<<M, 128>>>(gH, out);
}

// round 7
// speedup vs baseline: 1.9688x; 1.2179x over previous
#include <cuda_runtime.h>
#include <math_constants.h>
#include <cstdint>
#include <cstddef>

// Problem constants
#define HH 8
#define KD 64
#define VD 64
#define KNN 128
#define DM 512
#define FCD 2048
#define NB 4
#define SSQ 1024
#define EPS 1e-5f

// ---------------- scratch (single __device__ array, no allocations) ----------------
constexpr size_t OFF_GDEC = 0;
constexpr size_t OFF_GENC = OFF_GDEC + (size_t)SSQ * SSQ;
constexpr size_t OFF_K    = OFF_GENC + (size_t)SSQ * SSQ;
constexpr size_t OFF_V    = OFF_K   + (size_t)HH * NB * SSQ * KD;
constexpr size_t OFF_Q    = OFF_V   + (size_t)HH * NB * SSQ * VD;
constexpr size_t OFF_CTX  = OFF_Q   + (size_t)HH * NB * SSQ * KD;
constexpr size_t OFF_H    = OFF_CTX + (size_t)NB * SSQ * DM;
constexpr size_t OFF_H2   = OFF_H   + (size_t)NB * SSQ * DM;
constexpr size_t OFF_T    = OFF_H2  + (size_t)NB * SSQ * DM;
constexpr size_t OFF_ATT  = OFF_T   + (size_t)NB * SSQ * FCD;
constexpr size_t SCRATCH_TOTAL = OFF_ATT + (size_t)HH * NB * SSQ * SSQ;

__device__ float g_scratch[SCRATCH_TOTAL];

// ---------------- TF32 helpers ----------------
__device__ __forceinline__ uint32_t f2tf32(float f) {
    uint32_t o;
    asm("cvt.rna.tf32.f32 %0, %1;" : "=r"(o) : "f"(f));
    return o;
}

__device__ __forceinline__ void mma_tf32(float c[4],
                                         const uint32_t a[4],
                                         const uint32_t b[2])
{
    asm volatile(
        "mma.sync.aligned.m16n8k8.row.col.f32.tf32.tf32.f32 "
        "{%0,%1,%2,%3}, {%4,%5,%6,%7}, {%8,%9}, {%0,%1,%2,%3};"
        : "+f"(c[0]), "+f"(c[1]), "+f"(c[2]), "+f"(c[3])
        : "r"(a[0]), "r"(a[1]), "r"(a[2]), "r"(a[3]),
          "r"(b[0]), "r"(b[1]));
}

// ---------------- batched TF32 tensor-core GEMM ----------------
// C = alpha*A@B(^T) [+bias][relu][+resid]
// Block tile 128(M) x 64(N), K-tile 16, 256 threads = 8 warps (4x2),
// warp tile 32x32 = 2x4 m16n8k8 fragments, double-buffered smem.
// Requirements: M % 128 == 0, Nc % 64 == 0, Kc % 16 == 0 (true for all calls).
__global__ __launch_bounds__(256) void gemm_k(
    const float* __restrict__ A, const float* __restrict__ B, float* __restrict__ C,
    int Nc, int Kc, int ldc,
    long long sAo, long long sAi, long long sBo, long long sBi,
    long long sCo, long long sCi, int Bi,
    const float* __restrict__ bias, long long sBias,
    const float* __restrict__ resid, int ldr,
    float alpha, int transB, int relu)
{
    __shared__ uint32_t As[2][16][132];   // [buf][k][m] tf32 bits, pad 132 (2-way max)
    __shared__ uint32_t Bs[2][16][68];    // [buf][k][n] tf32 bits

    int z = blockIdx.z;
    int zo = z / Bi, zi = z - zo * Bi;
    A += (size_t)zo * sAo + (size_t)zi * sAi;
    B += (size_t)zo * sBo + (size_t)zi * sBi;
    C += (size_t)zo * sCo + (size_t)zi * sCi;
    const float* biasp = bias ? (bias + (size_t)zo * sBias) : nullptr;

    int bn0 = blockIdx.x * 64;
    int bm0 = blockIdx.y * 128;
    int t = threadIdx.x;
    int lane = t & 31, w = t >> 5;
    int wm = w >> 1, wn = w & 1;          // 4 x 2 warp grid
    int gid = lane >> 2, tg = lane & 3;
    int mb = wm * 32, nb = wn * 32;

    // A loader: 128 rows x 4 float4 (16 k) = 512 float4, 2 per thread
    int a_row0 = t >> 2,         a_kq0 = t & 3;
    int a_row1 = (t + 256) >> 2, a_kq1 = (t + 256) & 3;
    // B non-trans: 16 rows(k) x 16 float4(n) = 256, 1 per thread
    int b_kk = t >> 4, b_nq = t & 15;
    // B trans: 64 rows(n) x 4 float4(k) = 256, 1 per thread
    int bt_n = t >> 2, bt_kq = t & 3;

    float acc[2][4][4] = {};

    // ---- prologue: tile 0 ----
    {
        float4 v0 = *(const float4*)&A[(size_t)(bm0 + a_row0) * Kc + a_kq0 * 4];
        float4 v1 = *(const float4*)&A[(size_t)(bm0 + a_row1) * Kc + a_kq1 * 4];
        As[0][a_kq0 * 4 + 0][a_row0] = f2tf32(v0.x); As[0][a_kq0 * 4 + 1][a_row0] = f2tf32(v0.y);
        As[0][a_kq0 * 4 + 2][a_row0] = f2tf32(v0.z); As[0][a_kq0 * 4 + 3][a_row0] = f2tf32(v0.w);
        As[0][a_kq1 * 4 + 0][a_row1] = f2tf32(v1.x); As[0][a_kq1 * 4 + 1][a_row1] = f2tf32(v1.y);
        As[0][a_kq1 * 4 + 2][a_row1] = f2tf32(v1.z); As[0][a_kq1 * 4 + 3][a_row1] = f2tf32(v1.w);
        if (!transB) {
            float4 v = *(const float4*)&B[(size_t)b_kk * Nc + bn0 + b_nq * 4];
            Bs[0][b_kk][b_nq * 4 + 0] = f2tf32(v.x); Bs[0][b_kk][b_nq * 4 + 1] = f2tf32(v.y);
            Bs[0][b_kk][b_nq * 4 + 2] = f2tf32(v.z); Bs[0][b_kk][b_nq * 4 + 3] = f2tf32(v.w);
        } else {
            float4 v = *(const float4*)&B[(size_t)(bn0 + bt_n) * Kc + bt_kq * 4];
            Bs[0][bt_kq * 4 + 0][bt_n] = f2tf32(v.x); Bs[0][bt_kq * 4 + 1][bt_n] = f2tf32(v.y);
            Bs[0][bt_kq * 4 + 2][bt_n] = f2tf32(v.z); Bs[0][bt_kq * 4 + 3][bt_n] = f2tf32(v.w);
        }
    }
    __syncthreads();

    int nT = Kc >> 4;
    int cur = 0;
    for (int tt = 0; tt < nT; tt++) {
        float4 pa0, pa1, pb;
        bool has = (tt + 1) < nT;
        if (has) {
            int k0 = (tt + 1) << 4;
            pa0 = *(const float4*)&A[(size_t)(bm0 + a_row0) * Kc + k0 + a_kq0 * 4];
            pa1 = *(const float4*)&A[(size_t)(bm0 + a_row1) * Kc + k0 + a_kq1 * 4];
            if (!transB)
                pb = *(const float4*)&B[(size_t)(k0 + b_kk) * Nc + bn0 + b_nq * 4];
            else
                pb = *(const float4*)&B[(size_t)(bn0 + bt_n) * Kc + k0 + bt_kq * 4];
        }

        #pragma unroll
        for (int ks = 0; ks < 16; ks += 8) {
            uint32_t af[2][4], bf[4][2];
            #pragma unroll
            for (int mi = 0; mi < 2; mi++) {
                int m = mb + mi * 16 + gid;
                af[mi][0] = As[cur][ks + tg][m];
                af[mi][1] = As[cur][ks + tg][m + 8];
                af[mi][2] = As[cur][ks + tg + 4][m];
                af[mi][3] = As[cur][ks + tg + 4][m + 8];
            }
            #pragma unroll
            for (int nj = 0; nj < 4; nj++) {
                int n = nb + nj * 8 + gid;
                bf[nj][0] = Bs[cur][ks + tg][n];
                bf[nj][1] = Bs[cur][ks + tg + 4][n];
            }
            #pragma unroll
            for (int mi = 0; mi < 2; mi++)
                #pragma unroll
                for (int nj = 0; nj < 4; nj++)
                    mma_tf32(acc[mi][nj], af[mi], bf[nj]);
        }

        if (has) {
            int nxt = cur ^ 1;
            As[nxt][a_kq0 * 4 + 0][a_row0] = f2tf32(pa0.x); As[nxt][a_kq0 * 4 + 1][a_row0] = f2tf32(pa0.y);
            As[nxt][a_kq0 * 4 + 2][a_row0] = f2tf32(pa0.z); As[nxt][a_kq0 * 4 + 3][a_row0] = f2tf32(pa0.w);
            As[nxt][a_kq1 * 4 + 0][a_row1] = f2tf32(pa1.x); As[nxt][a_kq1 * 4 + 1][a_row1] = f2tf32(pa1.y);
            As[nxt][a_kq1 * 4 + 2][a_row1] = f2tf32(pa1.z); As[nxt][a_kq1 * 4 + 3][a_row1] = f2tf32(pa1.w);
            if (!transB) {
                Bs[nxt][b_kk][b_nq * 4 + 0] = f2tf32(pb.x); Bs[nxt][b_kk][b_nq * 4 + 1] = f2tf32(pb.y);
                Bs[nxt][b_kk][b_nq * 4 + 2] = f2tf32(pb.z); Bs[nxt][b_kk][b_nq * 4 + 3] = f2tf32(pb.w);
            } else {
                Bs[nxt][bt_kq * 4 + 0][bt_n] = f2tf32(pb.x); Bs[nxt][bt_kq * 4 + 1][bt_n] = f2tf32(pb.y);
                Bs[nxt][bt_kq * 4 + 2][bt_n] = f2tf32(pb.z); Bs[nxt][bt_kq * 4 + 3][bt_n] = f2tf32(pb.w);
            }
            __syncthreads();
            cur = nxt;
        }
    }

    // ---- epilogue ----
    // C fragment layout: c0:(g,2tg) c1:(g,2tg+1) c2:(g+8,2tg) c3:(g+8,2tg+1)
    #pragma unroll
    for (int mi = 0; mi < 2; mi++) {
        int r0 = bm0 + mb + mi * 16 + gid;
        #pragma unroll
        for (int nj = 0; nj < 4; nj++) {
            int cc = bn0 + nb + nj * 8 + 2 * tg;
            float b0 = 0.f, b1 = 0.f;
            if (biasp) { b0 = biasp[cc]; b1 = biasp[cc + 1]; }
            #pragma unroll
            for (int half = 0; half < 2; half++) {
                int row = r0 + half * 8;
                float vx = acc[mi][nj][half * 2 + 0] * alpha + b0;
                float vy = acc[mi][nj][half * 2 + 1] * alpha + b1;
                if (relu) { vx = fmaxf(vx, 0.f); vy = fmaxf(vy, 0.f); }
                if (resid) {
                    float2 r = *(const float2*)&resid[(size_t)row * ldr + cc];
                    vx += r.x; vy += r.y;
                }
                float2 o; o.x = vx; o.y = vy;
                *(float2*)&C[(size_t)row * ldc + cc] = o;
            }
        }
    }
}

// ---------------- row softmax (graph preprocessing), rows of length SSQ ----------------
__global__ __launch_bounds__(256) void row_softmax_k(const float* __restrict__ in,
                                                     float* __restrict__ out)
{
    __shared__ float sh[8];
    int row = blockIdx.x;
    int t = threadIdx.x;
    int lane = t & 31, w = t >> 5;
    const float* rin = in + (size_t)row * SSQ;
    float* rout = out + (size_t)row * SSQ;

    float v[4];
    #pragma unroll
    for (int i = 0; i < 4; i++) v[i] = rin[t + i * 256];

    float m = fmaxf(fmaxf(v[0], v[1]), fmaxf(v[2], v[3]));
    #pragma unroll
    for (int o = 16; o; o >>= 1) m = fmaxf(m, __shfl_xor_sync(0xffffffffu, m, o));
    if (lane == 0) sh[w] = m;
    __syncthreads();
    m = sh[0];
    #pragma unroll
    for (int i = 1; i < 8; i++) m = fmaxf(m, sh[i]);
    __syncthreads();

    float e[4]; float s = 0.f;
    #pragma unroll
    for (int i = 0; i < 4; i++) { e[i] = expf(v[i] - m); s += e[i]; }
    #pragma unroll
    for (int o = 16; o; o >>= 1) s += __shfl_xor_sync(0xffffffffu, s, o);
    if (lane == 0) sh[w] = s;
    __syncthreads();
    s = 0.f;
    #pragma unroll
    for (int i = 0; i < 8; i++) s += sh[i];
    float inv = 1.0f / s;
    #pragma unroll
    for (int i = 0; i < 4; i++) rout[t + i * 256] = e[i] * inv;
}

// ---------------- fused: causal mask + exact top-KNN threshold + softmax + graph blend ----------------
__device__ __forceinline__ unsigned f2key(float f) {
    unsigned u = __float_as_uint(f);
    return (u & 0x80000000u) ? ~u : (u | 0x80000000u);
}

__global__ __launch_bounds__(256) void attn_post_k(float* __restrict__ att,
                                                   const float* __restrict__ graph,
                                                   int masked, float gw)
{
    __shared__ float sredf[8];
    __shared__ unsigned scount[2][8];

    int q = blockIdx.x, n = blockIdx.y, h = blockIdx.z;
    float* row = att + (((size_t)(h * NB + n)) * SSQ + q) * SSQ;
    const float* grow = graph + (size_t)q * SSQ;
    int L = masked ? (q + 1) : SSQ;

    int t = threadIdx.x;
    int lane = t & 31, w = t >> 5;

    float v[4]; unsigned key[4]; bool valid[4];
    #pragma unroll
    for (int i = 0; i < 4; i++) {
        int idx = t + i * 256;
        valid[i] = idx < L;
        v[i] = valid[i] ? row[idx] : -CUDART_INF_F;
        key[i] = valid[i] ? f2key(v[i]) : 0u;
    }

    unsigned threshKey = 0;
    if (L > KNN) {
        unsigned lo = 0u, hi = 0xFFFFFFFFu;
        unsigned it = 0;
        while (lo < hi) {
            unsigned mid = (unsigned)((((unsigned long long)lo + (unsigned long long)hi + 1ull)) >> 1);
            unsigned c = 0;
            #pragma unroll
            for (int i = 0; i < 4; i++) c += (key[i] >= mid) ? 1u : 0u;
            #pragma unroll
            for (int o = 16; o; o >>= 1) c += __shfl_xor_sync(0xffffffffu, c, o);
            unsigned* sc = scount[it & 1];
            if (lane == 0) sc[w] = c;
            __syncthreads();
            unsigned cnt = 0;
            #pragma unroll
            for (int i = 0; i < 8; i++) cnt += sc[i];
            if (cnt >= KNN) lo = mid; else hi = mid - 1u;
            it++;
        }
        threshKey = lo;
    }

    bool kept[4];
    #pragma unroll
    for (int i = 0; i < 4; i++)
        kept[i] = valid[i] && (L <= KNN || key[i] >= threshKey);

    float m = -CUDART_INF_F;
    #pragma unroll
    for (int i = 0; i < 4; i++) if (kept[i]) m = fmaxf(m, v[i]);
    #pragma unroll
    for (int o = 16; o; o >>= 1) m = fmaxf(m, __shfl_xor_sync(0xffffffffu, m, o));
    __syncthreads();   // protect sredf reuse vs earlier scount reads
    if (lane == 0) sredf[w] = m;
    __syncthreads();
    m = sredf[0];
    #pragma unroll
    for (int i = 1; i < 8; i++) m = fmaxf(m, sredf[i]);
    __syncthreads();

    float e[4]; float s = 0.f;
    #pragma unroll
    for (int i = 0; i < 4; i++) {
        e[i] = kept[i] ? expf(v[i] - m) : 0.f;
        s += e[i];
    }
    #pragma unroll
    for (int o = 16; o; o >>= 1) s += __shfl_xor_sync(0xffffffffu, s, o);
    if (lane == 0) sredf[w] = s;
    __syncthreads();
    s = 0.f;
    #pragma unroll
    for (int i = 0; i < 8; i++) s += sredf[i];
    float inv = 1.0f / s;

    float og = 1.0f - gw;
    #pragma unroll
    for (int i = 0; i < 4; i++) {
        int idx = t + i * 256;
        row[idx] = gw * grow[idx] + og * (e[i] * inv);
    }
}

// ---------------- LayerNorm over rows of DM=512 (elementwise_affine=False) ----------------
__global__ __launch_bounds__(128) void layernorm_k(const float* __restrict__ in,
                                                   float* __restrict__ out)
{
    __shared__ float sh[4];
    int row = blockIdx.x;
    int t = threadIdx.x;
    int lane = t & 31, w = t >> 5;
    const float* rin = in + (size_t)row * DM;
    float* rout = out + (size_t)row * DM;

    float v[4];
    #pragma unroll
    for (int i = 0; i < 4; i++) v[i] = rin[t + i * 128];

    float s = v[0] + v[1] + v[2] + v[3];
    #pragma unroll
    for (int o = 16; o; o >>= 1) s += __shfl_xor_sync(0xffffffffu, s, o);
    if (lane == 0) sh[w] = s;
    __syncthreads();
    s = sh[0] + sh[1] + sh[2] + sh[3];
    float mean = s * (1.0f / DM);
    __syncthreads();

    float sq = 0.f;
    #pragma unroll
    for (int i = 0; i < 4; i++) { float d = v[i] - mean; sq += d * d; }
    #pragma unroll
    for (int o = 16; o; o >>= 1) sq += __shfl_xor_sync(0xffffffffu, sq, o);
    if (lane == 0) sh[w] = sq;
    __syncthreads();
    sq = sh[0] + sh[1] + sh[2] + sh[3];
    float var = sq * (1.0f / DM);
    float inv = rsqrtf(var + EPS);

    #pragma unroll
    for (int i = 0; i < 4; i++) rout[t + i * 128] = (v[i] - mean) * inv;
}

// ---------------- host-side helpers ----------------
static inline void gemm(const float* A, const float* B, float* C,
                        int M, int Nc, int Kc, int ldc,
                        long long sAo, long long sAi, long long sBo, long long sBi,
                        long long sCo, long long sCi, int Bo, int Bi,
                        const float* bias, long long sBias,
                        const float* resid, int ldr,
                        float alpha, int transB, int relu)
{
    dim3 grid(Nc / 64, M / 128, Bo * Bi), block(256);
    gemm_k<<<grid, block>>>(A, B, C, Nc, Kc, ldc, sAo, sAi, sBo, sBi, sCo, sCi, Bi,
                            bias, sBias, resid, ldr, alpha, transB, relu);
}

extern "C" void kernel_launch(void* const* d_in, const int* in_sizes, int n_in,
                              void* d_out, int out_size)
{
    (void)in_sizes; (void)n_in; (void)out_size;
    const float* z        = (const float*)d_in[0];
    const float* y        = (const float*)d_in[1];
    const float* graphDec = (const float*)d_in[2];
    const float* graphEnc = (const float*)d_in[3];
    const float* dec_Wk   = (const float*)d_in[4];
    const float* dec_bk   = (const float*)d_in[5];
    const float* dec_Wv   = (const float*)d_in[6];
    const float* dec_bv   = (const float*)d_in[7];
    const float* dec_Wo   = (const float*)d_in[8];
    const float* dec_bo   = (const float*)d_in[9];
    const float* enc_Wk   = (const float*)d_in[10];
    const float* enc_bk   = (const float*)d_in[11];
    const float* enc_Wq   = (const float*)d_in[12];
    const float* enc_bq   = (const float*)d_in[13];
    const float* enc_Wv   = (const float*)d_in[14];
    const float* enc_bv   = (const float*)d_in[15];
    const float* enc_Wo   = (const float*)d_in[16];
    const float* enc_bo   = (const float*)d_in[17];
    const float* fc_W1    = (const float*)d_in[18];
    const float* fc_b1    = (const float*)d_in[19];
    const float* fc_W2    = (const float*)d_in[20];
    const float* fc_b2    = (const float*)d_in[21];
    float* out = (float*)d_out;

    float* sc = nullptr;
    cudaGetSymbolAddress((void**)&sc, g_scratch);
    float* gdec = sc + OFF_GDEC;
    float* genc = sc + OFF_GENC;
    float* gK   = sc + OFF_K;
    float* gV   = sc + OFF_V;
    float* gQ   = sc + OFF_Q;
    float* gCtx = sc + OFF_CTX;
    float* gH   = sc + OFF_H;
    float* gH2  = sc + OFF_H2;
    float* gT   = sc + OFF_T;
    float* gAtt = sc + OFF_ATT;

    const int M = NB * SSQ;               // 4096
    const long long sKh = (long long)NB * SSQ * KD;  // per-head stride in K/V/Q
    const long long sKn = (long long)SSQ * KD;       // per-batch stride
    const long long sAh = (long long)NB * SSQ * SSQ; // att per-head
    const long long sAn = (long long)SSQ * SSQ;      // att per-batch
    const float inv_scale = 0.125f;       // 1/sqrt(64)

    // 0) graph row-softmax
    row_softmax_k<<<SSQ, 256>>>(graphDec, gdec);
    row_softmax_k<<<SSQ, 256>>>(graphEnc, genc);

    // ---------- stage 1: masked decoder self-attention on y ----------
    gemm(y, dec_Wk, gK, M, KD, DM, KD, 0, 0, (long long)DM * KD, 0, sKh, 0, HH, 1,
         dec_bk, KD, nullptr, 0, 1.0f, 0, 0);
    gemm(y, dec_Wv, gV, M, VD, DM, VD, 0, 0, (long long)DM * VD, 0, sKh, 0, HH, 1,
         dec_bv, VD, nullptr, 0, 1.0f, 0, 0);
    gemm(gK, gK, gAtt, SSQ, SSQ, KD, SSQ, sKh, sKn, sKh, sKn, sAh, sAn, HH, NB,
         nullptr, 0, nullptr, 0, inv_scale, 1, 0);
    attn_post_k<<<dim3(SSQ, NB, HH), 256>>>(gAtt, gdec, 1, 0.5f);
    gemm(gAtt, gV, gCtx, SSQ, VD, SSQ, DM, sAh, sAn, sKh, sKn, (long long)VD, (long long)SSQ * DM,
         HH, NB, nullptr, 0, nullptr, 0, 1.0f, 0, 0);
    gemm(gCtx, dec_Wo, gH, M, DM, DM, DM, 0, 0, 0, 0, 0, 0, 1, 1,
         dec_bo, 0, y, DM, 1.0f, 0, 0);
    layernorm_k<<<M, 128>>>(gH, gH);      // gH = h

    // ---------- stage 2: encoder-decoder attention (K,V from z, Q from h) ----------
    gemm(z, enc_Wk, gK, M, KD, DM, KD, 0, 0, (long long)DM * KD, 0, sKh, 0, HH, 1,
         enc_bk, KD, nullptr, 0, 1.0f, 0, 0);
    gemm(z, enc_Wv, gV, M, VD, DM, VD, 0, 0, (long long)DM * VD, 0, sKh, 0, HH, 1,
         enc_bv, VD, nullptr, 0, 1.0f, 0, 0);
    gemm(gH, enc_Wq, gQ, M, KD, DM, KD, 0, 0, (long long)DM * KD, 0, sKh, 0, HH, 1,
         enc_bq, KD, nullptr, 0, 1.0f, 0, 0);
    gemm(gQ, gK, gAtt, SSQ, SSQ, KD, SSQ, sKh, sKn, sKh, sKn, sAh, sAn, HH, NB,
         nullptr, 0, nullptr, 0, inv_scale, 1, 0);
    attn_post_k<<<dim3(SSQ, NB, HH), 256>>>(gAtt, genc, 0, 0.5f);
    gemm(gAtt, gV, gCtx, SSQ, VD, SSQ, DM, sAh, sAn, sKh, sKn, (long long)VD, (long long)SSQ * DM,
         HH, NB, nullptr, 0, nullptr, 0, 1.0f, 0, 0);
    gemm(gCtx, enc_Wo, gH2, M, DM, DM, DM, 0, 0, 0, 0, 0, 0, 1, 1,
         enc_bo, 0, gH, DM, 1.0f, 0, 0);
    layernorm_k<<<M, 128>>>(gH2, gH2);    // gH2 = h2

    // ---------- stage 3: MLP ----------
    gemm(gH2, fc_W1, gT, M, FCD, DM, FCD, 0, 0, 0, 0, 0, 0, 1, 1,
         fc_b1, 0, nullptr, 0, 1.0f, 0, 1);                 // relu
    gemm(gT, fc_W2, gH, M, DM, FCD, DM, 0, 0, 0, 0, 0, 0, 1, 1,
         fc_b2, 0, gH2, DM, 1.0f, 0, 0);                    // + residual h2
    layernorm_k<<<M, 128>>>(gH, out);
}